// round 1
// baseline (speedup 1.0000x reference)
#include <cuda_runtime.h>
#include <cuda_bf16.h>
#include <cstdint>

#define NATOMS_MAX   50000
#define NBONDS_MAX   500000
#define NTRIPLES_MAX 2000000
#define DIM 64   // feature dim, 16 float4 per row

// Scratch (allocation-free rule: __device__ globals).
// g_S must be zero at the start of every replay; fuse_kernel resets it after reading.
__device__ float g_U[NATOMS_MAX * DIM];    // sigmoid(A @ Wu + bu)
__device__ float g_S[NBONDS_MAX * DIM];    // segment-summed messages (zero-init at load)

// ---------------------------------------------------------------------------
// K1: U = sigmoid(A @ W + b).  64 rows per block, 256 threads, 4x4 microtile.
// ---------------------------------------------------------------------------
__global__ void __launch_bounds__(256)
update_kernel(const float* __restrict__ A,
              const float* __restrict__ W,
              const float* __restrict__ bvec,
              int nrows)
{
    __shared__ float  Xs[DIM][DIM + 1];     // transposed-access safe via padding
    __shared__ float4 Ws[DIM][16];          // W row-major, float4 packed
    __shared__ float4 bs[16];

    const int tid = threadIdx.x;
    const float4* Wv = reinterpret_cast<const float4*>(W);
    float4* WsLin = reinterpret_cast<float4*>(Ws);
#pragma unroll
    for (int i = 0; i < 4; ++i) WsLin[tid + i * 256] = Wv[tid + i * 256];
    if (tid < 16) bs[tid] = reinterpret_cast<const float4*>(bvec)[tid];

    const int rowBase = blockIdx.x * DIM;
    const float4* Av = reinterpret_cast<const float4*>(A);
#pragma unroll
    for (int i = 0; i < 4; ++i) {
        int idx = tid + i * 256;
        int r = idx >> 4, c4 = idx & 15;
        int row = rowBase + r;
        float4 v = (row < nrows) ? __ldg(&Av[row * 16 + c4]) : make_float4(0.f, 0.f, 0.f, 0.f);
        Xs[r][c4 * 4 + 0] = v.x; Xs[r][c4 * 4 + 1] = v.y;
        Xs[r][c4 * 4 + 2] = v.z; Xs[r][c4 * 4 + 3] = v.w;
    }
    __syncthreads();

    const int tx = tid & 15;        // col group (4 cols)
    const int ty = tid >> 4;        // row group (4 rows)
    const int r0 = 4 * ty;

    float acc[4][4];
#pragma unroll
    for (int i = 0; i < 4; ++i)
#pragma unroll
        for (int j = 0; j < 4; ++j) acc[i][j] = 0.f;

#pragma unroll 8
    for (int k = 0; k < DIM; ++k) {
        float4 w = Ws[k][tx];
        float a0 = Xs[r0 + 0][k], a1 = Xs[r0 + 1][k];
        float a2 = Xs[r0 + 2][k], a3 = Xs[r0 + 3][k];
        acc[0][0] += a0 * w.x; acc[0][1] += a0 * w.y; acc[0][2] += a0 * w.z; acc[0][3] += a0 * w.w;
        acc[1][0] += a1 * w.x; acc[1][1] += a1 * w.y; acc[1][2] += a1 * w.z; acc[1][3] += a1 * w.w;
        acc[2][0] += a2 * w.x; acc[2][1] += a2 * w.y; acc[2][2] += a2 * w.z; acc[2][3] += a2 * w.w;
        acc[3][0] += a3 * w.x; acc[3][1] += a3 * w.y; acc[3][2] += a3 * w.z; acc[3][3] += a3 * w.w;
    }

    float4 bb = bs[tx];
    float4* Uv = reinterpret_cast<float4*>(g_U);
#pragma unroll
    for (int i = 0; i < 4; ++i) {
        int row = rowBase + r0 + i;
        if (row < nrows) {
            float4 r;
            r.x = 1.f / (1.f + __expf(-(acc[i][0] + bb.x)));
            r.y = 1.f / (1.f + __expf(-(acc[i][1] + bb.y)));
            r.z = 1.f / (1.f + __expf(-(acc[i][2] + bb.z)));
            r.w = 1.f / (1.f + __expf(-(acc[i][3] + bb.w)));
            Uv[row * 16 + tx] = r;
        }
    }
}

// ---------------------------------------------------------------------------
// K2: per-triple message + segment-sum via 16B vector reductions.
// 16 threads per triple, one float4 each.
// ---------------------------------------------------------------------------
__global__ void __launch_bounds__(256)
scatter_kernel(const float4* __restrict__ basis,   // [n_triples*16]
               const int2*   __restrict__ tbi,     // triple_bond_indices
               const int*    __restrict__ bai,     // bond_atom_indices (flat)
               int n_triples)
{
    const int tid = blockIdx.x * 256 + threadIdx.x;
    const int triple = tid >> 4;
    if (triple >= n_triples) return;
    const int q = tid & 15;

    int2 tb = __ldg(&tbi[triple]);
    int third = __ldg(&bai[2 * tb.y + 1]);

    float4 b = __ldg(&basis[triple * 16 + q]);
    float4 u = __ldg(&reinterpret_cast<const float4*>(g_U)[third * 16 + q]);

    float4 m = make_float4(b.x * u.x, b.y * u.y, b.z * u.z, b.w * u.w);

    float4* p = &reinterpret_cast<float4*>(g_S)[tb.x * 16 + q];
    asm volatile("red.global.add.v4.f32 [%0], {%1, %2, %3, %4};"
                 :: "l"(p), "f"(m.x), "f"(m.y), "f"(m.z), "f"(m.w)
                 : "memory");
}

// ---------------------------------------------------------------------------
// K3: out = bond + S @ Wf + bf, then reset S to zero (replay-safe accumulator).
// ---------------------------------------------------------------------------
__global__ void __launch_bounds__(256)
fuse_kernel(const float* __restrict__ W,
            const float* __restrict__ bvec,
            const float* __restrict__ bond,
            float* __restrict__ out,
            int nrows)
{
    __shared__ float  Xs[DIM][DIM + 1];
    __shared__ float4 Ws[DIM][16];
    __shared__ float4 bs[16];

    const int tid = threadIdx.x;
    const float4* Wv = reinterpret_cast<const float4*>(W);
    float4* WsLin = reinterpret_cast<float4*>(Ws);
#pragma unroll
    for (int i = 0; i < 4; ++i) WsLin[tid + i * 256] = Wv[tid + i * 256];
    if (tid < 16) bs[tid] = reinterpret_cast<const float4*>(bvec)[tid];

    const int rowBase = blockIdx.x * DIM;
    const float4* Sv = reinterpret_cast<const float4*>(g_S);
#pragma unroll
    for (int i = 0; i < 4; ++i) {
        int idx = tid + i * 256;
        int r = idx >> 4, c4 = idx & 15;
        int row = rowBase + r;
        float4 v = (row < nrows) ? Sv[row * 16 + c4] : make_float4(0.f, 0.f, 0.f, 0.f);
        Xs[r][c4 * 4 + 0] = v.x; Xs[r][c4 * 4 + 1] = v.y;
        Xs[r][c4 * 4 + 2] = v.z; Xs[r][c4 * 4 + 3] = v.w;
    }
    __syncthreads();

    const int tx = tid & 15;
    const int ty = tid >> 4;
    const int r0 = 4 * ty;

    float acc[4][4];
#pragma unroll
    for (int i = 0; i < 4; ++i)
#pragma unroll
        for (int j = 0; j < 4; ++j) acc[i][j] = 0.f;

#pragma unroll 8
    for (int k = 0; k < DIM; ++k) {
        float4 w = Ws[k][tx];
        float a0 = Xs[r0 + 0][k], a1 = Xs[r0 + 1][k];
        float a2 = Xs[r0 + 2][k], a3 = Xs[r0 + 3][k];
        acc[0][0] += a0 * w.x; acc[0][1] += a0 * w.y; acc[0][2] += a0 * w.z; acc[0][3] += a0 * w.w;
        acc[1][0] += a1 * w.x; acc[1][1] += a1 * w.y; acc[1][2] += a1 * w.z; acc[1][3] += a1 * w.w;
        acc[2][0] += a2 * w.x; acc[2][1] += a2 * w.y; acc[2][2] += a2 * w.z; acc[2][3] += a2 * w.w;
        acc[3][0] += a3 * w.x; acc[3][1] += a3 * w.y; acc[3][2] += a3 * w.z; acc[3][3] += a3 * w.w;
    }

    float4 bb = bs[tx];
    const float4* bondv = reinterpret_cast<const float4*>(bond);
    float4* outv = reinterpret_cast<float4*>(out);
    float4* Sw = reinterpret_cast<float4*>(g_S);
    const float4 zero4 = make_float4(0.f, 0.f, 0.f, 0.f);
#pragma unroll
    for (int i = 0; i < 4; ++i) {
        int row = rowBase + r0 + i;
        if (row < nrows) {
            float4 bo = __ldg(&bondv[row * 16 + tx]);
            float4 r;
            r.x = acc[i][0] + bb.x + bo.x;
            r.y = acc[i][1] + bb.y + bo.y;
            r.z = acc[i][2] + bb.z + bo.z;
            r.w = acc[i][3] + bb.w + bo.w;
            outv[row * 16 + tx] = r;
            Sw[row * 16 + tx] = zero4;   // reset accumulator for next graph replay
        }
    }
}

// ---------------------------------------------------------------------------
extern "C" void kernel_launch(void* const* d_in, const int* in_sizes, int n_in,
                              void* d_out, int out_size)
{
    const float* atom  = (const float*)d_in[0];   // [N_ATOMS, 64]
    const float* bond  = (const float*)d_in[1];   // [N_BONDS, 64]
    const float* basis = (const float*)d_in[2];   // [N_TRIPLES, 64]
    const int*   bai   = (const int*)  d_in[3];   // [N_BONDS, 2]
    const int2*  tbi   = (const int2*) d_in[4];   // [N_TRIPLES, 2]
    const float* Wu    = (const float*)d_in[5];
    const float* bu    = (const float*)d_in[6];
    const float* Wf    = (const float*)d_in[7];
    const float* bf    = (const float*)d_in[8];
    float* out = (float*)d_out;

    const int n_atoms   = in_sizes[0] / DIM;
    const int n_bonds   = in_sizes[1] / DIM;
    const int n_triples = in_sizes[2] / DIM;

    // K1: per-atom sigmoid MLP (hoisted out of the per-triple loop)
    {
        int blocks = (n_atoms + DIM - 1) / DIM;
        update_kernel<<<blocks, 256>>>(atom, Wu, bu, n_atoms);
    }
    // K2: gather U, multiply basis, vector-reduce into S
    {
        long long threads = (long long)n_triples * 16;
        int blocks = (int)((threads + 255) / 256);
        scatter_kernel<<<blocks, 256>>>((const float4*)basis, tbi, bai, n_triples);
    }
    // K3: fuse GEMM + bias + residual, reset S
    {
        int blocks = (n_bonds + DIM - 1) / DIM;
        fuse_kernel<<<blocks, 256>>>(Wf, bf, bond, out, n_bonds);
    }
}

// round 2
// speedup vs baseline: 1.0822x; 1.0822x over previous
#include <cuda_runtime.h>
#include <cuda_bf16.h>
#include <cstdint>

#define NATOMS_MAX   50000
#define NBONDS_MAX   500064
#define NTRIPLES_MAX 2000000
#define DIM 64                // feature dim, 16 float4 per row
#define SCAN_CHUNK 2048       // elements per scan block (256 thr x 8)
#define MAX_SCAN_BLOCKS 512

// Scratch (allocation-free rule: __device__ globals).
__device__ float g_U[NATOMS_MAX * DIM];          // sigmoid(A @ Wu + bu)
__device__ int   g_count[NBONDS_MAX];            // triples per bond (zero at load; reset by gather_fuse)
__device__ int   g_start[NBONDS_MAX];            // CSR start offsets (rewritten each call)
__device__ int   g_cursor[NBONDS_MAX];           // scatter cursors (rewritten each call)
__device__ int   g_blocksum[MAX_SCAN_BLOCKS];
__device__ int   g_blockoff[MAX_SCAN_BLOCKS];
__device__ int2  g_pairs[NTRIPLES_MAX];          // {triple_id, third_atom_id}

// ---------------------------------------------------------------------------
// K1: U = sigmoid(A @ W + b).  64 rows per block, 256 threads, 4x4 microtile.
// ---------------------------------------------------------------------------
__global__ void __launch_bounds__(256)
update_kernel(const float* __restrict__ A,
              const float* __restrict__ W,
              const float* __restrict__ bvec,
              int nrows)
{
    __shared__ float  Xs[DIM][DIM + 1];
    __shared__ float4 Ws[DIM][16];
    __shared__ float4 bs[16];

    const int tid = threadIdx.x;
    const float4* Wv = reinterpret_cast<const float4*>(W);
    float4* WsLin = reinterpret_cast<float4*>(Ws);
#pragma unroll
    for (int i = 0; i < 4; ++i) WsLin[tid + i * 256] = Wv[tid + i * 256];
    if (tid < 16) bs[tid] = reinterpret_cast<const float4*>(bvec)[tid];

    const int rowBase = blockIdx.x * DIM;
    const float4* Av = reinterpret_cast<const float4*>(A);
#pragma unroll
    for (int i = 0; i < 4; ++i) {
        int idx = tid + i * 256;
        int r = idx >> 4, c4 = idx & 15;
        int row = rowBase + r;
        float4 v = (row < nrows) ? __ldg(&Av[row * 16 + c4]) : make_float4(0.f, 0.f, 0.f, 0.f);
        Xs[r][c4 * 4 + 0] = v.x; Xs[r][c4 * 4 + 1] = v.y;
        Xs[r][c4 * 4 + 2] = v.z; Xs[r][c4 * 4 + 3] = v.w;
    }
    __syncthreads();

    const int tx = tid & 15;
    const int ty = tid >> 4;
    const int r0 = 4 * ty;

    float acc[4][4];
#pragma unroll
    for (int i = 0; i < 4; ++i)
#pragma unroll
        for (int j = 0; j < 4; ++j) acc[i][j] = 0.f;

#pragma unroll 8
    for (int k = 0; k < DIM; ++k) {
        float4 w = Ws[k][tx];
        float a0 = Xs[r0 + 0][k], a1 = Xs[r0 + 1][k];
        float a2 = Xs[r0 + 2][k], a3 = Xs[r0 + 3][k];
        acc[0][0] += a0 * w.x; acc[0][1] += a0 * w.y; acc[0][2] += a0 * w.z; acc[0][3] += a0 * w.w;
        acc[1][0] += a1 * w.x; acc[1][1] += a1 * w.y; acc[1][2] += a1 * w.z; acc[1][3] += a1 * w.w;
        acc[2][0] += a2 * w.x; acc[2][1] += a2 * w.y; acc[2][2] += a2 * w.z; acc[2][3] += a2 * w.w;
        acc[3][0] += a3 * w.x; acc[3][1] += a3 * w.y; acc[3][2] += a3 * w.z; acc[3][3] += a3 * w.w;
    }

    float4 bb = bs[tx];
    float4* Uv = reinterpret_cast<float4*>(g_U);
#pragma unroll
    for (int i = 0; i < 4; ++i) {
        int row = rowBase + r0 + i;
        if (row < nrows) {
            float4 r;
            r.x = 1.f / (1.f + __expf(-(acc[i][0] + bb.x)));
            r.y = 1.f / (1.f + __expf(-(acc[i][1] + bb.y)));
            r.z = 1.f / (1.f + __expf(-(acc[i][2] + bb.z)));
            r.w = 1.f / (1.f + __expf(-(acc[i][3] + bb.w)));
            Uv[row * 16 + tx] = r;
        }
    }
}

// ---------------------------------------------------------------------------
// K2a: histogram of triples per bond.
// ---------------------------------------------------------------------------
__global__ void __launch_bounds__(256)
hist_kernel(const int2* __restrict__ tbi, int n_triples)
{
    int t = blockIdx.x * 256 + threadIdx.x;
    if (t < n_triples) {
        int b = __ldg(&tbi[t]).x;
        atomicAdd(&g_count[b], 1);
    }
}

// ---------------------------------------------------------------------------
// K2b/c/d: 3-kernel exclusive prefix scan over g_count -> g_start, g_cursor.
// ---------------------------------------------------------------------------
__global__ void __launch_bounds__(256)
scanA_kernel(int n)
{
    __shared__ int buf[SCAN_CHUNK];
    __shared__ int sd[256];
    const int t = threadIdx.x;
    const int base = blockIdx.x * SCAN_CHUNK;

#pragma unroll
    for (int k = 0; k < 8; ++k) {
        int idx = base + k * 256 + t;
        buf[k * 256 + t] = (idx < n) ? g_count[idx] : 0;
    }
    __syncthreads();

    int vals[8]; int s = 0;
#pragma unroll
    for (int k = 0; k < 8; ++k) { int v = buf[t * 8 + k]; vals[k] = s; s += v; }
    sd[t] = s;
    __syncthreads();

    // inclusive Hillis-Steele over 256 thread totals
    for (int off = 1; off < 256; off <<= 1) {
        int y = (t >= off) ? sd[t - off] : 0;
        __syncthreads();
        sd[t] += y;
        __syncthreads();
    }
    int thr_excl = sd[t] - s;

#pragma unroll
    for (int k = 0; k < 8; ++k) buf[t * 8 + k] = thr_excl + vals[k];
    __syncthreads();
#pragma unroll
    for (int k = 0; k < 8; ++k) {
        int idx = base + k * 256 + t;
        if (idx < n) g_start[idx] = buf[k * 256 + t];
    }
    if (t == 255) g_blocksum[blockIdx.x] = sd[255];
}

__global__ void __launch_bounds__(256)
scanB_kernel(int nblocks)
{
    __shared__ int sd[256];
    const int t = threadIdx.x;
    int v = (t < nblocks) ? g_blocksum[t] : 0;
    sd[t] = v;
    __syncthreads();
    for (int off = 1; off < 256; off <<= 1) {
        int y = (t >= off) ? sd[t - off] : 0;
        __syncthreads();
        sd[t] += y;
        __syncthreads();
    }
    if (t < nblocks) g_blockoff[t] = sd[t] - v;   // exclusive
}

__global__ void __launch_bounds__(256)
scanC_kernel(int n)
{
    const int off = g_blockoff[blockIdx.x];
    const int base = blockIdx.x * SCAN_CHUNK;
#pragma unroll
    for (int k = 0; k < 8; ++k) {
        int idx = base + k * 256 + threadIdx.x;
        if (idx < n) {
            int v = g_start[idx] + off;
            g_start[idx]  = v;
            g_cursor[idx] = v;
        }
    }
}

// ---------------------------------------------------------------------------
// K2e: scatter {triple, third_atom} pairs into CSR slots.
// ---------------------------------------------------------------------------
__global__ void __launch_bounds__(256)
pairs_kernel(const int2* __restrict__ tbi, const int* __restrict__ bai, int n_triples)
{
    int t = blockIdx.x * 256 + threadIdx.x;
    if (t < n_triples) {
        int2 tb = __ldg(&tbi[t]);
        int third = __ldg(&bai[2 * tb.y + 1]);
        int pos = atomicAdd(&g_cursor[tb.x], 1);
        g_pairs[pos] = make_int2(t, third);
    }
}

// ---------------------------------------------------------------------------
// K3: fused gather segment-sum + GEMM + bias + residual.
// 64 bonds per block, 256 threads; 4 threads per bond in phase 1.
// Resets g_count for its bonds (replay-safe histogram).
// ---------------------------------------------------------------------------
__global__ void __launch_bounds__(256)
gather_fuse_kernel(const float4* __restrict__ basis,
                   const float* __restrict__ W,
                   const float* __restrict__ bvec,
                   const float* __restrict__ bond,
                   float* __restrict__ out,
                   int nrows)
{
    __shared__ float  Xs[DIM][DIM + 1];
    __shared__ float4 Ws[DIM][16];
    __shared__ float4 bs[16];

    const int tid = threadIdx.x;
    const float4* Wv = reinterpret_cast<const float4*>(W);
    float4* WsLin = reinterpret_cast<float4*>(Ws);
#pragma unroll
    for (int i = 0; i < 4; ++i) WsLin[tid + i * 256] = Wv[tid + i * 256];
    if (tid < 16) bs[tid] = reinterpret_cast<const float4*>(bvec)[tid];

    const int rowBase = blockIdx.x * DIM;

    // ---- Phase 1: per-bond register segment sum (4 threads / bond) ----
    const int r    = tid >> 2;          // 0..63  local bond
    const int lane = tid & 3;           // quarter of the 64-float row
    const int row  = rowBase + r;

    float4 a0 = make_float4(0.f,0.f,0.f,0.f), a1 = a0, a2 = a0, a3 = a0;

    if (row < nrows) {
        const int s = g_start[row];
        const int c = g_count[row];
        const float4* Uv = reinterpret_cast<const float4*>(g_U);
        const int qb = lane * 4;        // float4 offset within the row
        for (int j = 0; j < c; ++j) {
            int2 p = __ldg(&g_pairs[s + j]);
            const float4* brow = &basis[p.x * 16 + qb];
            const float4* urow = &Uv  [p.y * 16 + qb];
            float4 b0 = __ldg(brow + 0), b1 = __ldg(brow + 1),
                   b2 = __ldg(brow + 2), b3 = __ldg(brow + 3);
            float4 u0 = __ldg(urow + 0), u1 = __ldg(urow + 1),
                   u2 = __ldg(urow + 2), u3 = __ldg(urow + 3);
            a0.x += b0.x*u0.x; a0.y += b0.y*u0.y; a0.z += b0.z*u0.z; a0.w += b0.w*u0.w;
            a1.x += b1.x*u1.x; a1.y += b1.y*u1.y; a1.z += b1.z*u1.z; a1.w += b1.w*u1.w;
            a2.x += b2.x*u2.x; a2.y += b2.y*u2.y; a2.z += b2.z*u2.z; a2.w += b2.w*u2.w;
            a3.x += b3.x*u3.x; a3.y += b3.y*u3.y; a3.z += b3.z*u3.z; a3.w += b3.w*u3.w;
        }
    }

    // stage segment sums into smem (unconditional: zeros for OOR rows)
    {
        const int cb = lane * 16;
        Xs[r][cb + 0]  = a0.x; Xs[r][cb + 1]  = a0.y; Xs[r][cb + 2]  = a0.z; Xs[r][cb + 3]  = a0.w;
        Xs[r][cb + 4]  = a1.x; Xs[r][cb + 5]  = a1.y; Xs[r][cb + 6]  = a1.z; Xs[r][cb + 7]  = a1.w;
        Xs[r][cb + 8]  = a2.x; Xs[r][cb + 9]  = a2.y; Xs[r][cb + 10] = a2.z; Xs[r][cb + 11] = a2.w;
        Xs[r][cb + 12] = a3.x; Xs[r][cb + 13] = a3.y; Xs[r][cb + 14] = a3.z; Xs[r][cb + 15] = a3.w;
    }

    // reset histogram counters for next replay (this block owns these rows)
    if (tid < 64 && rowBase + tid < nrows) g_count[rowBase + tid] = 0;

    __syncthreads();

    // ---- Phase 2: 64x64 GEMM (S @ Wf), bias, residual ----
    const int tx = tid & 15;
    const int ty = tid >> 4;
    const int r0 = 4 * ty;

    float acc[4][4];
#pragma unroll
    for (int i = 0; i < 4; ++i)
#pragma unroll
        for (int j = 0; j < 4; ++j) acc[i][j] = 0.f;

#pragma unroll 8
    for (int k = 0; k < DIM; ++k) {
        float4 w = Ws[k][tx];
        float x0 = Xs[r0 + 0][k], x1 = Xs[r0 + 1][k];
        float x2 = Xs[r0 + 2][k], x3 = Xs[r0 + 3][k];
        acc[0][0] += x0 * w.x; acc[0][1] += x0 * w.y; acc[0][2] += x0 * w.z; acc[0][3] += x0 * w.w;
        acc[1][0] += x1 * w.x; acc[1][1] += x1 * w.y; acc[1][2] += x1 * w.z; acc[1][3] += x1 * w.w;
        acc[2][0] += x2 * w.x; acc[2][1] += x2 * w.y; acc[2][2] += x2 * w.z; acc[2][3] += x2 * w.w;
        acc[3][0] += x3 * w.x; acc[3][1] += x3 * w.y; acc[3][2] += x3 * w.z; acc[3][3] += x3 * w.w;
    }

    float4 bb = bs[tx];
    const float4* bondv = reinterpret_cast<const float4*>(bond);
    float4* outv = reinterpret_cast<float4*>(out);
#pragma unroll
    for (int i = 0; i < 4; ++i) {
        int orow = rowBase + r0 + i;
        if (orow < nrows) {
            float4 bo = __ldg(&bondv[orow * 16 + tx]);
            float4 rr;
            rr.x = acc[i][0] + bb.x + bo.x;
            rr.y = acc[i][1] + bb.y + bo.y;
            rr.z = acc[i][2] + bb.z + bo.z;
            rr.w = acc[i][3] + bb.w + bo.w;
            outv[orow * 16 + tx] = rr;
        }
    }
}

// ---------------------------------------------------------------------------
extern "C" void kernel_launch(void* const* d_in, const int* in_sizes, int n_in,
                              void* d_out, int out_size)
{
    const float* atom  = (const float*)d_in[0];
    const float* bond  = (const float*)d_in[1];
    const float* basis = (const float*)d_in[2];
    const int*   bai   = (const int*)  d_in[3];
    const int2*  tbi   = (const int2*) d_in[4];
    const float* Wu    = (const float*)d_in[5];
    const float* bu    = (const float*)d_in[6];
    const float* Wf    = (const float*)d_in[7];
    const float* bf    = (const float*)d_in[8];
    float* out = (float*)d_out;

    const int n_atoms   = in_sizes[0] / DIM;
    const int n_bonds   = in_sizes[1] / DIM;
    const int n_triples = in_sizes[2] / DIM;

    const int tb = (n_triples + 255) / 256;
    const int sb = (n_bonds + SCAN_CHUNK - 1) / SCAN_CHUNK;

    update_kernel<<<(n_atoms + DIM - 1) / DIM, 256>>>(atom, Wu, bu, n_atoms);
    hist_kernel<<<tb, 256>>>(tbi, n_triples);
    scanA_kernel<<<sb, 256>>>(n_bonds);
    scanB_kernel<<<1, 256>>>(sb);
    scanC_kernel<<<sb, 256>>>(n_bonds);
    pairs_kernel<<<tb, 256>>>(tbi, bai, n_triples);
    gather_fuse_kernel<<<(n_bonds + DIM - 1) / DIM, 256>>>(
        (const float4*)basis, Wf, bf, bond, out, n_bonds);
}